// round 15
// baseline (speedup 1.0000x reference)
#include <cuda_runtime.h>
#include <cuda_bf16.h>
#include <cstdint>
#include <cstddef>

// ---------------------------------------------------------------------------
// multilayer_message_passing: 2-layer hetero GraphSAGE.
// R15: R13/R14 base (539us). Pull: each warp handles 8 CONSECUTIVE nodes
//      (outer loop around the unchanged gather body) -> block-retirement
//      tail shrinks ~sqrt(8); sequential csr index stream per warp.
// ---------------------------------------------------------------------------

#define N_GENE_MAX 100000
#define N_DIS_MAX   50000
#define DIM 128
#define E_MAX 800000
#define SCAN_TILE 4096
#define NPW 8   // nodes per warp in the pull

__device__ float g_agg_d[(size_t)N_DIS_MAX  * DIM];
__device__ float g_agg_g[(size_t)N_GENE_MAX * DIM];
__device__ int g_cnt_d[N_DIS_MAX];
__device__ int g_cnt_g[N_GENE_MAX];
__device__ int g_off_d[N_DIS_MAX + 1];
__device__ int g_off_g[N_GENE_MAX + 1];
__device__ int g_cur_d[N_DIS_MAX];
__device__ int g_cur_g[N_GENE_MAX];
__device__ int g_csr_g2d[E_MAX];
__device__ int g_csr_d2g[E_MAX];
__device__ int g_tmp[N_DIS_MAX + N_GENE_MAX];
__device__ int g_part[128];
__device__ __align__(16) __nv_bfloat16 g_wimg[16][DIM * DIM];

// ---------------------------------------------------------------------------
__device__ __forceinline__ uint32_t smem_u32(const void* p) {
    uint32_t a;
    asm("{ .reg .u64 t; cvta.to.shared.u64 t, %1; cvt.u32.u64 %0, t; }" : "=r"(a) : "l"(p));
    return a;
}

#define LDMX4(r, addr)                                                         \
    asm volatile("ldmatrix.sync.aligned.m8n8.x4.shared.b16 {%0,%1,%2,%3}, [%4];" \
                 : "=r"((r)[0]), "=r"((r)[1]), "=r"((r)[2]), "=r"((r)[3])      \
                 : "r"(addr))

#define MMA16816(d, a, b0, b1)                                                 \
    asm volatile("mma.sync.aligned.m16n8k16.row.col.f32.bf16.bf16.f32 "        \
                 "{%0,%1,%2,%3}, {%4,%5,%6,%7}, {%8,%9}, {%0,%1,%2,%3};"       \
                 : "+f"((d)[0]), "+f"((d)[1]), "+f"((d)[2]), "+f"((d)[3])      \
                 : "r"((a)[0]), "r"((a)[1]), "r"((a)[2]), "r"((a)[3]),         \
                   "r"(b0), "r"(b1))

// ---------------------------------------------------------------------------
// CSR build
// ---------------------------------------------------------------------------
__global__ void zero2_kernel(int* __restrict__ a, int na, int* __restrict__ b, int nb) {
    int i = blockIdx.x * blockDim.x + threadIdx.x;
    if (i < na) a[i] = 0;
    if (i < nb) b[i] = 0;
}

__global__ void count2_kernel(const int* __restrict__ dst1, int* __restrict__ cnt1, int E1,
                              const int* __restrict__ dst2, int* __restrict__ cnt2, int E2) {
    int e = blockIdx.x * blockDim.x + threadIdx.x;
    if (e < E1) atomicAdd(&cnt1[dst1[e]], 1);
    else if (e < E1 + E2) atomicAdd(&cnt2[dst2[e - E1]], 1);
}

__global__ void __launch_bounds__(1024)
scan_p1_kernel(const int* __restrict__ cnt_d, int n_dis,
               const int* __restrict__ cnt_g, int n_gene,
               int* __restrict__ tmp, int* __restrict__ part) {
    __shared__ int wsum[32];
    const int n_tot = n_dis + n_gene;
    const int t = threadIdx.x, lane = t & 31, wid = t >> 5;
    const int base = blockIdx.x * SCAN_TILE + t * 4;

    int v[4];
#pragma unroll
    for (int j = 0; j < 4; j++) {
        int i = base + j;
        v[j] = (i < n_tot) ? (i < n_dis ? cnt_d[i] : cnt_g[i - n_dis]) : 0;
    }
    int tsum = v[0] + v[1] + v[2] + v[3];
    int x = tsum;
#pragma unroll
    for (int o = 1; o < 32; o <<= 1) {
        int y = __shfl_up_sync(0xffffffffu, x, o);
        if (lane >= o) x += y;
    }
    if (lane == 31) wsum[wid] = x;
    __syncthreads();
    if (wid == 0) {
        int s = wsum[lane];
#pragma unroll
        for (int o = 1; o < 32; o <<= 1) {
            int y = __shfl_up_sync(0xffffffffu, s, o);
            if (lane >= o) s += y;
        }
        wsum[lane] = s;
    }
    __syncthreads();
    int ex = (x - tsum) + (wid > 0 ? wsum[wid - 1] : 0);
#pragma unroll
    for (int j = 0; j < 4; j++) {
        int i = base + j;
        if (i < n_tot) tmp[i] = ex;
        ex += v[j];
    }
    if (t == 1023) part[blockIdx.x] = wsum[31];
}

__global__ void __launch_bounds__(128)
scan_p2_kernel(int* __restrict__ part, int nb) {
    __shared__ int wsum[4];
    const int t = threadIdx.x, lane = t & 31, wid = t >> 5;
    int v = (t < nb) ? part[t] : 0;
    int x = v;
#pragma unroll
    for (int o = 1; o < 32; o <<= 1) {
        int y = __shfl_up_sync(0xffffffffu, x, o);
        if (lane >= o) x += y;
    }
    if (lane == 31) wsum[wid] = x;
    __syncthreads();
    if (t == 0) {
        int c = 0;
#pragma unroll
        for (int q = 0; q < 4; q++) { int w = wsum[q]; wsum[q] = c; c += w; }
    }
    __syncthreads();
    if (t < nb) part[t] = (x - v) + wsum[wid];
}

__global__ void scan_p3_kernel(const int* __restrict__ tmp, const int* __restrict__ part,
                               int* __restrict__ off_d, int* __restrict__ cur_d, int n_dis,
                               int* __restrict__ off_g, int* __restrict__ cur_g, int n_gene,
                               int E1, int E2) {
    int i = blockIdx.x * blockDim.x + threadIdx.x;
    int n_tot = n_dis + n_gene;
    if (i < n_tot) {
        int ex = tmp[i] + part[i >> 12];
        if (i < n_dis) { off_d[i] = ex; cur_d[i] = ex; }
        else { int k = i - n_dis; int e = ex - E1; off_g[k] = e; cur_g[k] = e; }
    }
    if (i == 0) { off_d[n_dis] = E1; off_g[n_gene] = E2; }
}

__global__ void fill2_kernel(const int* __restrict__ src1, const int* __restrict__ dst1,
                             int* __restrict__ cur1, int* __restrict__ csr1, int E1,
                             const int* __restrict__ src2, const int* __restrict__ dst2,
                             int* __restrict__ cur2, int* __restrict__ csr2, int E2) {
    int e = blockIdx.x * blockDim.x + threadIdx.x;
    if (e < E1) {
        int p = atomicAdd(&cur1[dst1[e]], 1);
        csr1[p] = src1[e];
    } else if (e < E1 + E2) {
        int i = e - E1;
        int p = atomicAdd(&cur2[dst2[i]], 1);
        csr2[p] = src2[i];
    }
}

// ---------------------------------------------------------------------------
// fused pull: each warp handles NPW consecutive nodes; the per-node gather
// body is the unchanged R6 loop.
// ---------------------------------------------------------------------------
__global__ void __launch_bounds__(256)
pull_fused_kernel(const float* __restrict__ xg_src, const float* __restrict__ xd_src,
                  float* __restrict__ agg_d, float* __restrict__ agg_g,
                  const int* __restrict__ csr_g2d, const int* __restrict__ off_d,
                  const int* __restrict__ csr_d2g, const int* __restrict__ off_g,
                  int n_dis, int n_gene) {
    const int wi = (blockIdx.x * blockDim.x + threadIdx.x) >> 5;
    const int lane = threadIdx.x & 31;
    const int wd = (n_dis + NPW - 1) / NPW;
    const int wg = (n_gene + NPW - 1) / NPW;

    const float4* __restrict__ base;
    const int* __restrict__ csr;
    const int* __restrict__ off;
    float* aggp;
    int node0, nmax;
    if (wi < wd) {
        node0 = wi * NPW; nmax = n_dis;
        base = (const float4*)xg_src; csr = csr_g2d; off = off_d; aggp = agg_d;
    } else if (wi < wd + wg) {
        node0 = (wi - wd) * NPW; nmax = n_gene;
        base = (const float4*)xd_src; csr = csr_d2g; off = off_g; aggp = agg_g;
    } else return;

    const int node_end = (node0 + NPW < nmax) ? node0 + NPW : nmax;
    for (int node = node0; node < node_end; node++) {
        const int start = off[node], end = off[node + 1];
        float4 acc0 = make_float4(0.f, 0.f, 0.f, 0.f);
        float4 acc1 = make_float4(0.f, 0.f, 0.f, 0.f);
        int e = start;
        for (; e + 8 <= end; e += 8) {
            int s0 = csr[e],     s1 = csr[e + 1], s2 = csr[e + 2], s3 = csr[e + 3];
            int s4 = csr[e + 4], s5 = csr[e + 5], s6 = csr[e + 6], s7 = csr[e + 7];
            float4 a = base[(size_t)s0 * 32 + lane];
            float4 b = base[(size_t)s1 * 32 + lane];
            float4 c = base[(size_t)s2 * 32 + lane];
            float4 d = base[(size_t)s3 * 32 + lane];
            float4 p = base[(size_t)s4 * 32 + lane];
            float4 q = base[(size_t)s5 * 32 + lane];
            float4 r = base[(size_t)s6 * 32 + lane];
            float4 s = base[(size_t)s7 * 32 + lane];
            acc0.x += a.x + b.x; acc0.y += a.y + b.y; acc0.z += a.z + b.z; acc0.w += a.w + b.w;
            acc1.x += c.x + d.x; acc1.y += c.y + d.y; acc1.z += c.z + d.z; acc1.w += c.w + d.w;
            acc0.x += p.x + q.x; acc0.y += p.y + q.y; acc0.z += p.z + q.z; acc0.w += p.w + q.w;
            acc1.x += r.x + s.x; acc1.y += r.y + s.y; acc1.z += r.z + s.z; acc1.w += r.w + s.w;
        }
        for (; e + 2 <= end; e += 2) {
            float4 a = base[(size_t)csr[e] * 32 + lane];
            float4 b = base[(size_t)csr[e + 1] * 32 + lane];
            acc0.x += a.x; acc0.y += a.y; acc0.z += a.z; acc0.w += a.w;
            acc1.x += b.x; acc1.y += b.y; acc1.z += b.z; acc1.w += b.w;
        }
        if (e < end) {
            float4 a = base[(size_t)csr[e] * 32 + lane];
            acc0.x += a.x; acc0.y += a.y; acc0.z += a.z; acc0.w += a.w;
        }
        float inv = 1.0f / fmaxf((float)(end - start), 1.0f);
        float4 o;
        o.x = (acc0.x + acc1.x) * inv;
        o.y = (acc0.y + acc1.y) * inv;
        o.z = (acc0.z + acc1.z) * inv;
        o.w = (acc0.w + acc1.w) * inv;
        ((float4*)aggp)[(size_t)node * 32 + lane] = o;
    }
}

// bf16 hi/lo images of all 8 weight matrices (plain row-major)
__global__ void prep_w_kernel(const float* __restrict__ Wl, const float* __restrict__ Wr) {
    int mat = blockIdx.x;
    int lt = mat >> 1, which = mat & 1;
    const float* W = (which ? Wr : Wl) + (size_t)lt * DIM * DIM;
    __nv_bfloat16* ih = g_wimg[mat * 2 + 0];
    __nv_bfloat16* il = g_wimg[mat * 2 + 1];
    for (int i = threadIdx.x; i < DIM * DIM; i += blockDim.x) {
        float w = W[i];
        __nv_bfloat16 h = __float2bfloat16(w);
        ih[i] = h;
        il[i] = __float2bfloat16(w - __bfloat162float(h));
    }
}

// ---------------------------------------------------------------------------
// fused update, TM=64 nodes/CTA (105KB smem -> 2 CTA/SM). (EXACT R13/R14)
// ---------------------------------------------------------------------------
#define TM       64
#define ZSTRIDE  136
#define ZT_B     (TM * ZSTRIDE * 2)
#define WT_B     (DIM * ZSTRIDE * 2)
#define OFF_BIAS 0
#define OFF_ZH   1024
#define OFF_ZL   (OFF_ZH + ZT_B)
#define OFF_WH   (OFF_ZL + ZT_B)
#define OFF_WL   (OFF_WH + WT_B)
#define SMEM_TOT (OFF_WL + WT_B)
#define HSTRIDE  132

__global__ void __launch_bounds__(256)
update_fused_kernel(const float* __restrict__ agg_d, const float* __restrict__ xin_d,
                    float* __restrict__ xout_d, int n_d,
                    const float* __restrict__ agg_g, const float* __restrict__ xin_g,
                    float* __restrict__ xout_g, int n_g,
                    const __nv_bfloat16* __restrict__ wimg, const float* __restrict__ bias_base,
                    int layer, int nbd, int do_relu) {
    extern __shared__ __align__(16) unsigned char smem[];
    const uint32_t sbase = smem_u32(smem);
    const int t    = threadIdx.x;
    const int wid  = t >> 5;
    const int lane = t & 31;
    const int wm   = wid >> 2;
    const int wn   = wid & 3;
    const int r0   = wm * 32;

    const int is_g = (blockIdx.x >= nbd) ? 1 : 0;
    const int tile = (is_g ? (blockIdx.x - nbd) : blockIdx.x) * TM;
    const float* agg  = is_g ? agg_g : agg_d;
    const float* xin  = is_g ? xin_g : xin_d;
    float*       xout = is_g ? xout_g : xout_d;
    const int n = is_g ? n_g : n_d;
    const int lt = layer * 2 + is_g;
    const __nv_bfloat16* wl_hi = wimg + (size_t)(lt * 4 + 0) * DIM * DIM;
    const __nv_bfloat16* wl_lo = wimg + (size_t)(lt * 4 + 1) * DIM * DIM;
    const __nv_bfloat16* wr_hi = wimg + (size_t)(lt * 4 + 2) * DIM * DIM;
    const __nv_bfloat16* wr_lo = wimg + (size_t)(lt * 4 + 3) * DIM * DIM;
    const float* bias = bias_base + (size_t)lt * DIM;

    float* sbias = (float*)(smem + OFF_BIAS);
    if (t < 128) sbias[t] = bias[t];

    const uint32_t aoff =
        ((uint32_t)((r0 + ((lane >> 3) & 1) * 8 + (lane & 7)) * ZSTRIDE +
                    ((lane >> 4) & 1) * 8)) * 2;
    const uint32_t boff =
        ((uint32_t)((wn * 32 + ((lane >> 4) & 1) * 8 + (lane & 7)) * ZSTRIDE +
                    ((lane >> 3) & 1) * 8)) * 2;

    float acc[2][4][4];
#pragma unroll
    for (int f = 0; f < 2; f++)
#pragma unroll
        for (int j = 0; j < 4; j++)
#pragma unroll
            for (int c = 0; c < 4; c++) acc[f][j][c] = 0.0f;

    __nv_bfloat16* zh = (__nv_bfloat16*)(smem + OFF_ZH);
    __nv_bfloat16* zl = (__nv_bfloat16*)(smem + OFF_ZL);

    for (int phase = 0; phase < 2; phase++) {
        {
            const int k = t & 127;
            const float* zsrc = (phase == 0) ? agg : xin;
            for (int row = (t >> 7); row < TM; row += 2) {
                int ng = tile + row;
                float v = (ng < n) ? zsrc[(size_t)ng * DIM + k] : 0.0f;
                __nv_bfloat16 h = __float2bfloat16(v);
                zh[row * ZSTRIDE + k] = h;
                zl[row * ZSTRIDE + k] = __float2bfloat16(v - __bfloat162float(h));
            }
        }
        {
            const uint4* gh = (const uint4*)(phase == 0 ? wl_hi : wr_hi);
            const uint4* gl = (const uint4*)(phase == 0 ? wl_lo : wr_lo);
            for (int i = t; i < 2048; i += 256) {
                int j = i >> 4, kc = i & 15;
                uint32_t off = ((uint32_t)(j * ZSTRIDE + kc * 8)) * 2;
                *(uint4*)(smem + OFF_WH + off) = gh[i];
                *(uint4*)(smem + OFF_WL + off) = gl[i];
            }
        }
        __syncthreads();

        const uint32_t zh_a = sbase + OFF_ZH + aoff;
        const uint32_t wh_b = sbase + OFF_WH + boff;

#pragma unroll
        for (int ks = 0; ks < 8; ks++) {
            uint32_t azh[2][4], azl[2][4], bh[2][4], bl[2][4];
#pragma unroll
            for (int f = 0; f < 2; f++) {
                uint32_t a = zh_a + ks * 32 + f * (16 * ZSTRIDE * 2);
                LDMX4(azh[f], a);
                LDMX4(azl[f], a + ZT_B);
            }
#pragma unroll
            for (int q = 0; q < 2; q++) {
                uint32_t a = wh_b + ks * 32 + q * (16 * ZSTRIDE * 2);
                LDMX4(bh[q], a);
                LDMX4(bl[q], a + WT_B);
            }
#pragma unroll
            for (int f = 0; f < 2; f++)
#pragma unroll
                for (int j = 0; j < 4; j++) {
                    const int q = j >> 1, s = (j & 1) * 2;
                    MMA16816(acc[f][j], azh[f], bh[q][s], bh[q][s + 1]);
                    MMA16816(acc[f][j], azl[f], bh[q][s], bh[q][s + 1]);
                    MMA16816(acc[f][j], azh[f], bl[q][s], bl[q][s + 1]);
                }
        }
        __syncthreads();
    }

    // epilogue: acc -> f32 staging in dead W region; skip-sum from z tiles.
    float* sh = (float*)(smem + OFF_WH);
#pragma unroll
    for (int f = 0; f < 2; f++) {
        int row = r0 + f * 16 + (lane >> 2);
        int col = wn * 32 + (lane & 3) * 2;
#pragma unroll
        for (int j = 0; j < 4; j++) {
            int c = col + j * 8;
            sh[row * HSTRIDE + c]           = acc[f][j][0];
            sh[row * HSTRIDE + c + 1]       = acc[f][j][1];
            sh[(row + 8) * HSTRIDE + c]     = acc[f][j][2];
            sh[(row + 8) * HSTRIDE + c + 1] = acc[f][j][3];
        }
    }
    __syncthreads();

    {
        const int row = t >> 2;
        const int qd  = t & 3;
        const int c0  = qd * 32;
        float ssq = 0.0f;
        float h[32];
#pragma unroll
        for (int c = 0; c < 32; c++) {
            float v = sh[row * HSTRIDE + c0 + c] + sbias[c0 + c];
            if (do_relu) v = fmaxf(v, 0.0f);
            h[c] = v;
            ssq += v * v;
        }
        ssq += __shfl_xor_sync(0xffffffffu, ssq, 1);
        ssq += __shfl_xor_sync(0xffffffffu, ssq, 2);
        float sc = 1.0f / fmaxf(sqrtf(ssq), 1e-12f);

        int node = tile + row;
        if (node < n) {
            float4* xo = (float4*)(xout + (size_t)node * DIM + c0);
            const __nv_bfloat16* zhr = zh + row * ZSTRIDE + c0;
            const __nv_bfloat16* zlr = zl + row * ZSTRIDE + c0;
#pragma unroll
            for (int q = 0; q < 8; q++) {
                float4 o;
                o.x = __bfloat162float(zhr[q * 4 + 0]) + __bfloat162float(zlr[q * 4 + 0]) + h[q * 4 + 0] * sc;
                o.y = __bfloat162float(zhr[q * 4 + 1]) + __bfloat162float(zlr[q * 4 + 1]) + h[q * 4 + 1] * sc;
                o.z = __bfloat162float(zhr[q * 4 + 2]) + __bfloat162float(zlr[q * 4 + 2]) + h[q * 4 + 2] * sc;
                o.w = __bfloat162float(zhr[q * 4 + 3]) + __bfloat162float(zlr[q * 4 + 3]) + h[q * 4 + 3] * sc;
                xo[q] = o;
            }
        }
    }
}

// ---------------------------------------------------------------------------
extern "C" void kernel_launch(void* const* d_in, const int* in_sizes, int n_in,
                              void* d_out, int out_size) {
    const float* x_gene  = (const float*)d_in[0];
    const float* x_dis   = (const float*)d_in[1];
    const float* Wl      = (const float*)d_in[2];
    const float* Wr      = (const float*)d_in[3];
    const float* b       = (const float*)d_in[4];
    const int*   src_g2d = (const int*)d_in[5];
    const int*   dst_g2d = (const int*)d_in[6];
    const int*   src_d2g = (const int*)d_in[7];
    const int*   dst_d2g = (const int*)d_in[8];

    const int n_gene = in_sizes[0] / DIM;
    const int n_dis  = in_sizes[1] / DIM;
    const int E1 = in_sizes[5];
    const int E2 = in_sizes[7];

    float *agg_d, *agg_g;
    int *cnt_d, *cnt_g, *off_d, *off_g, *cur_d, *cur_g, *csr_g2d, *csr_d2g;
    int *tmp, *part;
    __nv_bfloat16* wimg;
    cudaGetSymbolAddress((void**)&agg_d, g_agg_d);
    cudaGetSymbolAddress((void**)&agg_g, g_agg_g);
    cudaGetSymbolAddress((void**)&cnt_d, g_cnt_d);
    cudaGetSymbolAddress((void**)&cnt_g, g_cnt_g);
    cudaGetSymbolAddress((void**)&off_d, g_off_d);
    cudaGetSymbolAddress((void**)&off_g, g_off_g);
    cudaGetSymbolAddress((void**)&cur_d, g_cur_d);
    cudaGetSymbolAddress((void**)&cur_g, g_cur_g);
    cudaGetSymbolAddress((void**)&csr_g2d, g_csr_g2d);
    cudaGetSymbolAddress((void**)&csr_d2g, g_csr_d2g);
    cudaGetSymbolAddress((void**)&tmp, g_tmp);
    cudaGetSymbolAddress((void**)&part, g_part);
    cudaGetSymbolAddress((void**)&wimg, g_wimg);

    float* xg = (float*)d_out;
    float* xd = xg + (size_t)n_gene * DIM;

    prep_w_kernel<<<8, 256>>>(Wl, Wr);

    // ---- CSR build ----
    const int n_tot = n_dis + n_gene;
    const int nz = (n_gene > n_dis ? n_gene : n_dis);
    const int nb_scan = (n_tot + SCAN_TILE - 1) / SCAN_TILE;
    zero2_kernel<<<(nz + 255) / 256, 256>>>(cnt_d, n_dis, cnt_g, n_gene);
    count2_kernel<<<(E1 + E2 + 255) / 256, 256>>>(dst_g2d, cnt_d, E1, dst_d2g, cnt_g, E2);
    scan_p1_kernel<<<nb_scan, 1024>>>(cnt_d, n_dis, cnt_g, n_gene, tmp, part);
    scan_p2_kernel<<<1, 128>>>(part, nb_scan);
    scan_p3_kernel<<<(n_tot + 255) / 256, 256>>>(tmp, part, off_d, cur_d, n_dis,
                                                 off_g, cur_g, n_gene, E1, E2);
    fill2_kernel<<<(E1 + E2 + 255) / 256, 256>>>(src_g2d, dst_g2d, cur_d, csr_g2d, E1,
                                                 src_d2g, dst_d2g, cur_g, csr_d2g, E2);

    cudaFuncSetAttribute(update_fused_kernel,
                         cudaFuncAttributeMaxDynamicSharedMemorySize, SMEM_TOT);

    const int nbd = (n_dis + TM - 1) / TM;
    const int nbg = (n_gene + TM - 1) / TM;
    const int wd = (n_dis + NPW - 1) / NPW;
    const int wg = (n_gene + NPW - 1) / NPW;
    const int pull_blocks = ((wd + wg) * 32 + 255) / 256;

    // ---- layer 0: read inputs directly ----
    pull_fused_kernel<<<pull_blocks, 256>>>(x_gene, x_dis, agg_d, agg_g,
                                            csr_g2d, off_d, csr_d2g, off_g,
                                            n_dis, n_gene);
    update_fused_kernel<<<nbd + nbg, 256, SMEM_TOT>>>(
        agg_d, x_dis, xd, n_dis, agg_g, x_gene, xg, n_gene,
        wimg, b, 0, nbd, 1);

    // ---- layer 1: in place on d_out ----
    pull_fused_kernel<<<pull_blocks, 256>>>(xg, xd, agg_d, agg_g,
                                            csr_g2d, off_d, csr_d2g, off_g,
                                            n_dis, n_gene);
    update_fused_kernel<<<nbd + nbg, 256, SMEM_TOT>>>(
        agg_d, xd, xd, n_dis, agg_g, xg, xg, n_gene,
        wimg, b, 1, nbd, 0);
}

// round 16
// speedup vs baseline: 1.1460x; 1.1460x over previous
#include <cuda_runtime.h>
#include <cuda_bf16.h>
#include <cstdint>
#include <cstddef>

// ---------------------------------------------------------------------------
// multilayer_message_passing: 2-layer hetero GraphSAGE.
// R16: exact R14 base (best, 539.5us) + (a) scan_p2 launch folded into
//      scan_p3 (local partial-prefix), (b) float4-vectorized z staging in
//      the update kernel. Pull untouched (frozen).
// ---------------------------------------------------------------------------

#define N_GENE_MAX 100000
#define N_DIS_MAX   50000
#define DIM 128
#define E_MAX 800000
#define SCAN_TILE 4096

__device__ float g_agg_d[(size_t)N_DIS_MAX  * DIM];
__device__ float g_agg_g[(size_t)N_GENE_MAX * DIM];
__device__ int g_cnt_d[N_DIS_MAX];
__device__ int g_cnt_g[N_GENE_MAX];
__device__ int g_off_d[N_DIS_MAX + 1];
__device__ int g_off_g[N_GENE_MAX + 1];
__device__ int g_cur_d[N_DIS_MAX];
__device__ int g_cur_g[N_GENE_MAX];
__device__ int g_csr_g2d[E_MAX];
__device__ int g_csr_d2g[E_MAX];
__device__ int g_tmp[N_DIS_MAX + N_GENE_MAX];
__device__ int g_part[128];
__device__ __align__(16) __nv_bfloat16 g_wimg[16][DIM * DIM];

// ---------------------------------------------------------------------------
__device__ __forceinline__ uint32_t smem_u32(const void* p) {
    uint32_t a;
    asm("{ .reg .u64 t; cvta.to.shared.u64 t, %1; cvt.u32.u64 %0, t; }" : "=r"(a) : "l"(p));
    return a;
}

#define LDMX4(r, addr)                                                         \
    asm volatile("ldmatrix.sync.aligned.m8n8.x4.shared.b16 {%0,%1,%2,%3}, [%4];" \
                 : "=r"((r)[0]), "=r"((r)[1]), "=r"((r)[2]), "=r"((r)[3])      \
                 : "r"(addr))

#define MMA16816(d, a, b0, b1)                                                 \
    asm volatile("mma.sync.aligned.m16n8k16.row.col.f32.bf16.bf16.f32 "        \
                 "{%0,%1,%2,%3}, {%4,%5,%6,%7}, {%8,%9}, {%0,%1,%2,%3};"       \
                 : "+f"((d)[0]), "+f"((d)[1]), "+f"((d)[2]), "+f"((d)[3])      \
                 : "r"((a)[0]), "r"((a)[1]), "r"((a)[2]), "r"((a)[3]),         \
                   "r"(b0), "r"(b1))

// ---------------------------------------------------------------------------
// CSR build
// ---------------------------------------------------------------------------
__global__ void zero2_kernel(int* __restrict__ a, int na, int* __restrict__ b, int nb) {
    int i = blockIdx.x * blockDim.x + threadIdx.x;
    if (i < na) a[i] = 0;
    if (i < nb) b[i] = 0;
}

__global__ void count2_kernel(const int* __restrict__ dst1, int* __restrict__ cnt1, int E1,
                              const int* __restrict__ dst2, int* __restrict__ cnt2, int E2) {
    int e = blockIdx.x * blockDim.x + threadIdx.x;
    if (e < E1) atomicAdd(&cnt1[dst1[e]], 1);
    else if (e < E1 + E2) atomicAdd(&cnt2[dst2[e - E1]], 1);
}

// phase 1: per-block local exclusive scan; part[b] = raw block sum.
__global__ void __launch_bounds__(1024)
scan_p1_kernel(const int* __restrict__ cnt_d, int n_dis,
               const int* __restrict__ cnt_g, int n_gene,
               int* __restrict__ tmp, int* __restrict__ part) {
    __shared__ int wsum[32];
    const int n_tot = n_dis + n_gene;
    const int t = threadIdx.x, lane = t & 31, wid = t >> 5;
    const int base = blockIdx.x * SCAN_TILE + t * 4;

    int v[4];
#pragma unroll
    for (int j = 0; j < 4; j++) {
        int i = base + j;
        v[j] = (i < n_tot) ? (i < n_dis ? cnt_d[i] : cnt_g[i - n_dis]) : 0;
    }
    int tsum = v[0] + v[1] + v[2] + v[3];
    int x = tsum;
#pragma unroll
    for (int o = 1; o < 32; o <<= 1) {
        int y = __shfl_up_sync(0xffffffffu, x, o);
        if (lane >= o) x += y;
    }
    if (lane == 31) wsum[wid] = x;
    __syncthreads();
    if (wid == 0) {
        int s = wsum[lane];
#pragma unroll
        for (int o = 1; o < 32; o <<= 1) {
            int y = __shfl_up_sync(0xffffffffu, s, o);
            if (lane >= o) s += y;
        }
        wsum[lane] = s;
    }
    __syncthreads();
    int ex = (x - tsum) + (wid > 0 ? wsum[wid - 1] : 0);
#pragma unroll
    for (int j = 0; j < 4; j++) {
        int i = base + j;
        if (i < n_tot) tmp[i] = ex;
        ex += v[j];
    }
    if (t == 1023) part[blockIdx.x] = wsum[31];   // raw sum of this block
}

// phase 3 (p2 folded in): local exclusive prefix of <=128 raw partials,
// then combine + split into off/cur.
__global__ void scan_p3_kernel(const int* __restrict__ tmp, const int* __restrict__ part,
                               int nb,
                               int* __restrict__ off_d, int* __restrict__ cur_d, int n_dis,
                               int* __restrict__ off_g, int* __restrict__ cur_g, int n_gene,
                               int E1, int E2) {
    __shared__ int spref[128];
    const int t = threadIdx.x;
    if (t == 0) {
        int c = 0;
        for (int q = 0; q < nb; q++) { spref[q] = c; c += part[q]; }
    }
    __syncthreads();

    int i = blockIdx.x * blockDim.x + t;
    int n_tot = n_dis + n_gene;
    if (i < n_tot) {
        int ex = tmp[i] + spref[i >> 12];   // SCAN_TILE == 4096
        if (i < n_dis) { off_d[i] = ex; cur_d[i] = ex; }
        else { int k = i - n_dis; int e = ex - E1; off_g[k] = e; cur_g[k] = e; }
    }
    if (i == 0) { off_d[n_dis] = E1; off_g[n_gene] = E2; }
}

__global__ void fill2_kernel(const int* __restrict__ src1, const int* __restrict__ dst1,
                             int* __restrict__ cur1, int* __restrict__ csr1, int E1,
                             const int* __restrict__ src2, const int* __restrict__ dst2,
                             int* __restrict__ cur2, int* __restrict__ csr2, int E2) {
    int e = blockIdx.x * blockDim.x + threadIdx.x;
    if (e < E1) {
        int p = atomicAdd(&cur1[dst1[e]], 1);
        csr1[p] = src1[e];
    } else if (e < E1 + E2) {
        int i = e - E1;
        int p = atomicAdd(&cur2[dst2[i]], 1);
        csr2[p] = src2[i];
    }
}

// ---------------------------------------------------------------------------
// fused pull aggregation (EXACT R10/R14, FROZEN): warp per dst node.
// ---------------------------------------------------------------------------
__global__ void __launch_bounds__(256)
pull_fused_kernel(const float* __restrict__ xg_src, const float* __restrict__ xd_src,
                  float* __restrict__ agg_d, float* __restrict__ agg_g,
                  const int* __restrict__ csr_g2d, const int* __restrict__ off_d,
                  const int* __restrict__ csr_d2g, const int* __restrict__ off_g,
                  int n_dis, int n_gene) {
    const int w = (blockIdx.x * blockDim.x + threadIdx.x) >> 5;
    const int lane = threadIdx.x & 31;
    const float4* __restrict__ base;
    const int* __restrict__ csr;
    const int* __restrict__ off;
    float* aggp;
    int node;
    if (w < n_dis) {
        node = w; base = (const float4*)xg_src; csr = csr_g2d; off = off_d;
        aggp = agg_d;
    } else if (w < n_dis + n_gene) {
        node = w - n_dis; base = (const float4*)xd_src; csr = csr_d2g; off = off_g;
        aggp = agg_g;
    } else return;

    const int start = off[node], end = off[node + 1];
    float4 acc0 = make_float4(0.f, 0.f, 0.f, 0.f);
    float4 acc1 = make_float4(0.f, 0.f, 0.f, 0.f);
    int e = start;
    for (; e + 8 <= end; e += 8) {
        int s0 = csr[e],     s1 = csr[e + 1], s2 = csr[e + 2], s3 = csr[e + 3];
        int s4 = csr[e + 4], s5 = csr[e + 5], s6 = csr[e + 6], s7 = csr[e + 7];
        float4 a = base[(size_t)s0 * 32 + lane];
        float4 b = base[(size_t)s1 * 32 + lane];
        float4 c = base[(size_t)s2 * 32 + lane];
        float4 d = base[(size_t)s3 * 32 + lane];
        float4 p = base[(size_t)s4 * 32 + lane];
        float4 q = base[(size_t)s5 * 32 + lane];
        float4 r = base[(size_t)s6 * 32 + lane];
        float4 s = base[(size_t)s7 * 32 + lane];
        acc0.x += a.x + b.x; acc0.y += a.y + b.y; acc0.z += a.z + b.z; acc0.w += a.w + b.w;
        acc1.x += c.x + d.x; acc1.y += c.y + d.y; acc1.z += c.z + d.z; acc1.w += c.w + d.w;
        acc0.x += p.x + q.x; acc0.y += p.y + q.y; acc0.z += p.z + q.z; acc0.w += p.w + q.w;
        acc1.x += r.x + s.x; acc1.y += r.y + s.y; acc1.z += r.z + s.z; acc1.w += r.w + s.w;
    }
    for (; e + 2 <= end; e += 2) {
        float4 a = base[(size_t)csr[e] * 32 + lane];
        float4 b = base[(size_t)csr[e + 1] * 32 + lane];
        acc0.x += a.x; acc0.y += a.y; acc0.z += a.z; acc0.w += a.w;
        acc1.x += b.x; acc1.y += b.y; acc1.z += b.z; acc1.w += b.w;
    }
    if (e < end) {
        float4 a = base[(size_t)csr[e] * 32 + lane];
        acc0.x += a.x; acc0.y += a.y; acc0.z += a.z; acc0.w += a.w;
    }
    float inv = 1.0f / fmaxf((float)(end - start), 1.0f);
    float4 o;
    o.x = (acc0.x + acc1.x) * inv;
    o.y = (acc0.y + acc1.y) * inv;
    o.z = (acc0.z + acc1.z) * inv;
    o.w = (acc0.w + acc1.w) * inv;
    ((float4*)aggp)[(size_t)node * 32 + lane] = o;
}

// bf16 hi/lo images of all 8 weight matrices (plain row-major)
__global__ void prep_w_kernel(const float* __restrict__ Wl, const float* __restrict__ Wr) {
    int mat = blockIdx.x;
    int lt = mat >> 1, which = mat & 1;
    const float* W = (which ? Wr : Wl) + (size_t)lt * DIM * DIM;
    __nv_bfloat16* ih = g_wimg[mat * 2 + 0];
    __nv_bfloat16* il = g_wimg[mat * 2 + 1];
    for (int i = threadIdx.x; i < DIM * DIM; i += blockDim.x) {
        float w = W[i];
        __nv_bfloat16 h = __float2bfloat16(w);
        ih[i] = h;
        il[i] = __float2bfloat16(w - __bfloat162float(h));
    }
}

// ---------------------------------------------------------------------------
// fused update, TM=64 nodes/CTA (105KB smem -> 2 CTA/SM).
// R16 delta vs R14: z staging via float4 loads + bfloat162 paired stores.
// ---------------------------------------------------------------------------
#define TM       64
#define ZSTRIDE  136
#define ZT_B     (TM * ZSTRIDE * 2)
#define WT_B     (DIM * ZSTRIDE * 2)
#define OFF_BIAS 0
#define OFF_ZH   1024
#define OFF_ZL   (OFF_ZH + ZT_B)
#define OFF_WH   (OFF_ZL + ZT_B)
#define OFF_WL   (OFF_WH + WT_B)
#define SMEM_TOT (OFF_WL + WT_B)
#define HSTRIDE  132

__global__ void __launch_bounds__(256)
update_fused_kernel(const float* __restrict__ agg_d, const float* __restrict__ xin_d,
                    float* __restrict__ xout_d, int n_d,
                    const float* __restrict__ agg_g, const float* __restrict__ xin_g,
                    float* __restrict__ xout_g, int n_g,
                    const __nv_bfloat16* __restrict__ wimg, const float* __restrict__ bias_base,
                    int layer, int nbd, int do_relu) {
    extern __shared__ __align__(16) unsigned char smem[];
    const uint32_t sbase = smem_u32(smem);
    const int t    = threadIdx.x;
    const int wid  = t >> 5;
    const int lane = t & 31;
    const int wm   = wid >> 2;
    const int wn   = wid & 3;
    const int r0   = wm * 32;

    const int is_g = (blockIdx.x >= nbd) ? 1 : 0;
    const int tile = (is_g ? (blockIdx.x - nbd) : blockIdx.x) * TM;
    const float* agg  = is_g ? agg_g : agg_d;
    const float* xin  = is_g ? xin_g : xin_d;
    float*       xout = is_g ? xout_g : xout_d;
    const int n = is_g ? n_g : n_d;
    const int lt = layer * 2 + is_g;
    const __nv_bfloat16* wl_hi = wimg + (size_t)(lt * 4 + 0) * DIM * DIM;
    const __nv_bfloat16* wl_lo = wimg + (size_t)(lt * 4 + 1) * DIM * DIM;
    const __nv_bfloat16* wr_hi = wimg + (size_t)(lt * 4 + 2) * DIM * DIM;
    const __nv_bfloat16* wr_lo = wimg + (size_t)(lt * 4 + 3) * DIM * DIM;
    const float* bias = bias_base + (size_t)lt * DIM;

    float* sbias = (float*)(smem + OFF_BIAS);
    if (t < 128) sbias[t] = bias[t];

    const uint32_t aoff =
        ((uint32_t)((r0 + ((lane >> 3) & 1) * 8 + (lane & 7)) * ZSTRIDE +
                    ((lane >> 4) & 1) * 8)) * 2;
    const uint32_t boff =
        ((uint32_t)((wn * 32 + ((lane >> 4) & 1) * 8 + (lane & 7)) * ZSTRIDE +
                    ((lane >> 3) & 1) * 8)) * 2;

    float acc[2][4][4];
#pragma unroll
    for (int f = 0; f < 2; f++)
#pragma unroll
        for (int j = 0; j < 4; j++)
#pragma unroll
            for (int c = 0; c < 4; c++) acc[f][j][c] = 0.0f;

    __nv_bfloat16* zh = (__nv_bfloat16*)(smem + OFF_ZH);
    __nv_bfloat16* zl = (__nv_bfloat16*)(smem + OFF_ZL);

    for (int phase = 0; phase < 2; phase++) {
        // ---- z staging: float4 loads (8 per thread), paired bf16x2 stores ----
        {
            const float* zsrc = (phase == 0) ? agg : xin;
            const float4* z4 = (const float4*)zsrc + (size_t)tile * 32;
            for (int i = t; i < TM * 32; i += 256) {
                int row = i >> 5, c4 = i & 31;
                float4 v = make_float4(0.f, 0.f, 0.f, 0.f);
                if (tile + row < n) v = z4[(size_t)row * 32 + c4];
                __nv_bfloat16 h0 = __float2bfloat16(v.x);
                __nv_bfloat16 h1 = __float2bfloat16(v.y);
                __nv_bfloat16 h2 = __float2bfloat16(v.z);
                __nv_bfloat16 h3 = __float2bfloat16(v.w);
                __nv_bfloat162 hp0; hp0.x = h0; hp0.y = h1;
                __nv_bfloat162 hp1; hp1.x = h2; hp1.y = h3;
                __nv_bfloat162 lp0;
                lp0.x = __float2bfloat16(v.x - __bfloat162float(h0));
                lp0.y = __float2bfloat16(v.y - __bfloat162float(h1));
                __nv_bfloat162 lp1;
                lp1.x = __float2bfloat16(v.z - __bfloat162float(h2));
                lp1.y = __float2bfloat16(v.w - __bfloat162float(h3));
                __nv_bfloat16* zhp = zh + row * ZSTRIDE + c4 * 4;
                __nv_bfloat16* zlp = zl + row * ZSTRIDE + c4 * 4;
                *(__nv_bfloat162*)(zhp)     = hp0;
                *(__nv_bfloat162*)(zhp + 2) = hp1;
                *(__nv_bfloat162*)(zlp)     = lp0;
                *(__nv_bfloat162*)(zlp + 2) = lp1;
            }
        }
        // ---- W tiles ----
        {
            const uint4* gh = (const uint4*)(phase == 0 ? wl_hi : wr_hi);
            const uint4* gl = (const uint4*)(phase == 0 ? wl_lo : wr_lo);
            for (int i = t; i < 2048; i += 256) {
                int j = i >> 4, kc = i & 15;
                uint32_t off = ((uint32_t)(j * ZSTRIDE + kc * 8)) * 2;
                *(uint4*)(smem + OFF_WH + off) = gh[i];
                *(uint4*)(smem + OFF_WL + off) = gl[i];
            }
        }
        __syncthreads();

        const uint32_t zh_a = sbase + OFF_ZH + aoff;
        const uint32_t wh_b = sbase + OFF_WH + boff;

#pragma unroll
        for (int ks = 0; ks < 8; ks++) {
            uint32_t azh[2][4], azl[2][4], bh[2][4], bl[2][4];
#pragma unroll
            for (int f = 0; f < 2; f++) {
                uint32_t a = zh_a + ks * 32 + f * (16 * ZSTRIDE * 2);
                LDMX4(azh[f], a);
                LDMX4(azl[f], a + ZT_B);
            }
#pragma unroll
            for (int q = 0; q < 2; q++) {
                uint32_t a = wh_b + ks * 32 + q * (16 * ZSTRIDE * 2);
                LDMX4(bh[q], a);
                LDMX4(bl[q], a + WT_B);
            }
#pragma unroll
            for (int f = 0; f < 2; f++)
#pragma unroll
                for (int j = 0; j < 4; j++) {
                    const int q = j >> 1, s = (j & 1) * 2;
                    MMA16816(acc[f][j], azh[f], bh[q][s], bh[q][s + 1]);
                    MMA16816(acc[f][j], azl[f], bh[q][s], bh[q][s + 1]);
                    MMA16816(acc[f][j], azh[f], bl[q][s], bl[q][s + 1]);
                }
        }
        __syncthreads();
    }

    // epilogue: acc -> f32 staging in dead W region; skip-sum from z tiles.
    float* sh = (float*)(smem + OFF_WH);
#pragma unroll
    for (int f = 0; f < 2; f++) {
        int row = r0 + f * 16 + (lane >> 2);
        int col = wn * 32 + (lane & 3) * 2;
#pragma unroll
        for (int j = 0; j < 4; j++) {
            int c = col + j * 8;
            sh[row * HSTRIDE + c]           = acc[f][j][0];
            sh[row * HSTRIDE + c + 1]       = acc[f][j][1];
            sh[(row + 8) * HSTRIDE + c]     = acc[f][j][2];
            sh[(row + 8) * HSTRIDE + c + 1] = acc[f][j][3];
        }
    }
    __syncthreads();

    {
        const int row = t >> 2;
        const int qd  = t & 3;
        const int c0  = qd * 32;
        float ssq = 0.0f;
        float h[32];
#pragma unroll
        for (int c = 0; c < 32; c++) {
            float v = sh[row * HSTRIDE + c0 + c] + sbias[c0 + c];
            if (do_relu) v = fmaxf(v, 0.0f);
            h[c] = v;
            ssq += v * v;
        }
        ssq += __shfl_xor_sync(0xffffffffu, ssq, 1);
        ssq += __shfl_xor_sync(0xffffffffu, ssq, 2);
        float sc = 1.0f / fmaxf(sqrtf(ssq), 1e-12f);

        int node = tile + row;
        if (node < n) {
            float4* xo = (float4*)(xout + (size_t)node * DIM + c0);
            const __nv_bfloat16* zhr = zh + row * ZSTRIDE + c0;
            const __nv_bfloat16* zlr = zl + row * ZSTRIDE + c0;
#pragma unroll
            for (int q = 0; q < 8; q++) {
                float4 o;
                o.x = __bfloat162float(zhr[q * 4 + 0]) + __bfloat162float(zlr[q * 4 + 0]) + h[q * 4 + 0] * sc;
                o.y = __bfloat162float(zhr[q * 4 + 1]) + __bfloat162float(zlr[q * 4 + 1]) + h[q * 4 + 1] * sc;
                o.z = __bfloat162float(zhr[q * 4 + 2]) + __bfloat162float(zlr[q * 4 + 2]) + h[q * 4 + 2] * sc;
                o.w = __bfloat162float(zhr[q * 4 + 3]) + __bfloat162float(zlr[q * 4 + 3]) + h[q * 4 + 3] * sc;
                xo[q] = o;
            }
        }
    }
}

// ---------------------------------------------------------------------------
extern "C" void kernel_launch(void* const* d_in, const int* in_sizes, int n_in,
                              void* d_out, int out_size) {
    const float* x_gene  = (const float*)d_in[0];
    const float* x_dis   = (const float*)d_in[1];
    const float* Wl      = (const float*)d_in[2];
    const float* Wr      = (const float*)d_in[3];
    const float* b       = (const float*)d_in[4];
    const int*   src_g2d = (const int*)d_in[5];
    const int*   dst_g2d = (const int*)d_in[6];
    const int*   src_d2g = (const int*)d_in[7];
    const int*   dst_d2g = (const int*)d_in[8];

    const int n_gene = in_sizes[0] / DIM;
    const int n_dis  = in_sizes[1] / DIM;
    const int E1 = in_sizes[5];
    const int E2 = in_sizes[7];

    float *agg_d, *agg_g;
    int *cnt_d, *cnt_g, *off_d, *off_g, *cur_d, *cur_g, *csr_g2d, *csr_d2g;
    int *tmp, *part;
    __nv_bfloat16* wimg;
    cudaGetSymbolAddress((void**)&agg_d, g_agg_d);
    cudaGetSymbolAddress((void**)&agg_g, g_agg_g);
    cudaGetSymbolAddress((void**)&cnt_d, g_cnt_d);
    cudaGetSymbolAddress((void**)&cnt_g, g_cnt_g);
    cudaGetSymbolAddress((void**)&off_d, g_off_d);
    cudaGetSymbolAddress((void**)&off_g, g_off_g);
    cudaGetSymbolAddress((void**)&cur_d, g_cur_d);
    cudaGetSymbolAddress((void**)&cur_g, g_cur_g);
    cudaGetSymbolAddress((void**)&csr_g2d, g_csr_g2d);
    cudaGetSymbolAddress((void**)&csr_d2g, g_csr_d2g);
    cudaGetSymbolAddress((void**)&tmp, g_tmp);
    cudaGetSymbolAddress((void**)&part, g_part);
    cudaGetSymbolAddress((void**)&wimg, g_wimg);

    float* xg = (float*)d_out;
    float* xd = xg + (size_t)n_gene * DIM;

    prep_w_kernel<<<8, 256>>>(Wl, Wr);

    // ---- CSR build ----
    const int n_tot = n_dis + n_gene;
    const int nz = (n_gene > n_dis ? n_gene : n_dis);
    const int nb_scan = (n_tot + SCAN_TILE - 1) / SCAN_TILE;
    zero2_kernel<<<(nz + 255) / 256, 256>>>(cnt_d, n_dis, cnt_g, n_gene);
    count2_kernel<<<(E1 + E2 + 255) / 256, 256>>>(dst_g2d, cnt_d, E1, dst_d2g, cnt_g, E2);
    scan_p1_kernel<<<nb_scan, 1024>>>(cnt_d, n_dis, cnt_g, n_gene, tmp, part);
    scan_p3_kernel<<<(n_tot + 255) / 256, 256>>>(tmp, part, nb_scan,
                                                 off_d, cur_d, n_dis,
                                                 off_g, cur_g, n_gene, E1, E2);
    fill2_kernel<<<(E1 + E2 + 255) / 256, 256>>>(src_g2d, dst_g2d, cur_d, csr_g2d, E1,
                                                 src_d2g, dst_d2g, cur_g, csr_d2g, E2);

    cudaFuncSetAttribute(update_fused_kernel,
                         cudaFuncAttributeMaxDynamicSharedMemorySize, SMEM_TOT);

    const int nbd = (n_dis + TM - 1) / TM;
    const int nbg = (n_gene + TM - 1) / TM;
    const int pull_blocks = ((n_dis + n_gene) * 32 + 255) / 256;

    // ---- layer 0: read inputs directly ----
    pull_fused_kernel<<<pull_blocks, 256>>>(x_gene, x_dis, agg_d, agg_g,
                                            csr_g2d, off_d, csr_d2g, off_g,
                                            n_dis, n_gene);
    update_fused_kernel<<<nbd + nbg, 256, SMEM_TOT>>>(
        agg_d, x_dis, xd, n_dis, agg_g, x_gene, xg, n_gene,
        wimg, b, 0, nbd, 1);

    // ---- layer 1: in place on d_out ----
    pull_fused_kernel<<<pull_blocks, 256>>>(xg, xd, agg_d, agg_g,
                                            csr_g2d, off_d, csr_d2g, off_g,
                                            n_dis, n_gene);
    update_fused_kernel<<<nbd + nbg, 256, SMEM_TOT>>>(
        agg_d, xd, xd, n_dis, agg_g, xg, xg, n_gene,
        wimg, b, 1, nbd, 0);
}